// round 15
// baseline (speedup 1.0000x reference)
#include <cuda_runtime.h>
#include <float.h>
#include <math.h>
#include <stdint.h>

// Problem constants
#define N_TOK   32768
#define DIM     512
#define NTYPE   26
#define PER     128
#define NCODE   (NTYPE*PER)     // 3328
#define SAMP    312
#define ND      (N_TOK*DIM)     // 16777216
#define TEMP    0.07f
#define COMMIT  0.25f
#define KC      32
#define NCHUNK  (DIM/KC)        // 16

// -------- scratch (device globals; no allocation allowed) --------
__device__ float  g_ne[NCODE*DIM];                // normalized embeddings
__device__ __align__(128) float g_ebT[NCODE*DIM]; // raw emb, [type][k][code]
__device__ float  g_en2[NCODE];
__device__ int    g_count[NTYPE];
__device__ int    g_offset[NTYPE];
__device__ int    g_cursor[NTYPE];
__device__ int    g_order[N_TOK];
__device__ int    g_work[512];
__device__ int    g_nwork;
__device__ int    g_ticket;
__device__ int    g_uticket;
__device__ int    g_ctadone;
__device__ int    g_hist_done;
__device__ int    g_scan_done;
__device__ double g_diff_acc;
__device__ double g_uloss_acc;

// -------- helpers --------
__device__ __forceinline__ uint32_t smem_u32(const void* p) {
    uint32_t a;
    asm("{ .reg .u64 t; cvta.to.shared.u64 t, %1; cvt.u32.u64 %0, t; }" : "=r"(a) : "l"(p));
    return a;
}
#define CP_ASYNC16(dst, src) \
    asm volatile("cp.async.cg.shared.global [%0], [%1], 16;" :: "r"(dst), "l"(src))
#define CP_COMMIT() asm volatile("cp.async.commit_group;")
#define CP_WAIT0()  asm volatile("cp.async.wait_group 0;")

// -------- kernels --------
__global__ void k_init() {
    int t = threadIdx.x;
    if (t < NTYPE) g_count[t] = 0;
    if (t == 0) {
        g_diff_acc = 0.0; g_uloss_acc = 0.0;
        g_ticket = 0; g_uticket = 0; g_ctadone = 0;
        g_hist_done = 0; g_scan_done = 0;
    }
}

// block per code row: norm2 + normalized row + transposed raw copy
__global__ void k_norm_emb(const float* __restrict__ emb) {
    int row = blockIdx.x;
    int t = threadIdx.x;
    float4 a = ((const float4*)(emb + (size_t)row * DIM))[t];
    float s = a.x*a.x + a.y*a.y + a.z*a.z + a.w*a.w;
    #pragma unroll
    for (int o = 16; o; o >>= 1) s += __shfl_xor_sync(0xffffffffu, s, o);
    __shared__ float ws[4];
    if ((t & 31) == 0) ws[t >> 5] = s;
    __syncthreads();
    float tot = ws[0] + ws[1] + ws[2] + ws[3];
    if (t == 0) g_en2[row] = tot;
    float inv = 1.0f / fmaxf(sqrtf(tot), 1e-12f);
    ((float4*)(g_ne + (size_t)row * DIM))[t] =
        make_float4(a.x*inv, a.y*inv, a.z*inv, a.w*inv);
    int type = row >> 7, code = row & 127;
    size_t base = ((size_t)type * DIM + 4*t) * PER + code;
    g_ebT[base          ] = a.x;
    g_ebT[base +     PER] = a.y;
    g_ebT[base + 2 * PER] = a.z;
    g_ebT[base + 3 * PER] = a.w;
}

// fused hist + scan/worklist + scatter (64 resident blocks, spin barriers)
__global__ void k_histscat(const int* __restrict__ Q) {
    __shared__ int h[NTYPE], base[NTYPE];
    int tid = threadIdx.x;
    if (tid < NTYPE) h[tid] = 0;
    __syncthreads();
    int per = (N_TOK + gridDim.x - 1) / gridDim.x;
    int s = blockIdx.x * per;
    int e = min(s + per, N_TOK);
    for (int i = s + tid; i < e; i += blockDim.x)
        atomicAdd(&h[Q[i]], 1);
    __syncthreads();
    if (tid < NTYPE && h[tid]) atomicAdd(&g_count[tid], h[tid]);
    __threadfence();
    __syncthreads();
    if (tid == 0) atomicAdd(&g_hist_done, 1);

    if (blockIdx.x == 0) {
        if (tid == 0) while (atomicAdd(&g_hist_done, 0) < (int)gridDim.x) {}
        __syncthreads();
        if (tid < 32) {
            int lane = tid;
            int c = (lane < NTYPE) ? g_count[lane] : 0;
            int tiles = (c + 127) / 128;
            int sc = c, st = tiles;
            #pragma unroll
            for (int o = 1; o < 32; o <<= 1) {
                int v = __shfl_up_sync(0xffffffffu, sc, o);
                int w = __shfl_up_sync(0xffffffffu, st, o);
                if (lane >= o) { sc += v; st += w; }
            }
            int off = sc - c, toff = st - tiles;
            if (lane < NTYPE) {
                g_offset[lane] = off;
                g_cursor[lane] = off;
                for (int t2 = 0; t2 < tiles; t2++) g_work[toff + t2] = (lane << 8) | t2;
            }
            int tot = __shfl_sync(0xffffffffu, st, NTYPE - 1);
            if (lane == 0) {
                g_nwork = tot;
                __threadfence();
                atomicExch(&g_scan_done, 1);
            }
        }
        __syncthreads();
    } else {
        if (tid == 0) while (atomicAdd(&g_scan_done, 0) == 0) {}
        __syncthreads();
    }

    if (tid < NTYPE) {
        base[tid] = (h[tid] > 0) ? atomicAdd(&g_cursor[tid], h[tid]) : 0;
        h[tid] = 0;
    }
    __syncthreads();
    for (int i = s + tid; i < e; i += blockDim.x) {
        int t = Q[i];
        g_order[base[t] + atomicAdd(&h[t], 1)] = i;
    }
}

// Persistent SCALAR-FFMA GEMM (R5 inner loop), double-buffered:
// B via cp.async from g_ebT, A prefetched via 16 regs; + all fusions.
// Dynamic smem floats: A0@0 A1@4096 B0@8192 B1@12288 (4 x 16KB = 64KB).
__global__ __launch_bounds__(256, 2) void k_argmin(const float* __restrict__ x,
                                                   const int* __restrict__ samp,
                                                   float* __restrict__ out) {
    extern __shared__ __align__(16) float dynsm[];
    __shared__ int   toks[128];
    __shared__ float snorm[128];
    __shared__ float sen2[128];
    __shared__ int   scodes[128];
    __shared__ int   s_work;
    __shared__ float red[256];
    __shared__ float wsum[8], wpos[8];

    int tid = threadIdx.x;
    int tx = tid & 15, ty = tid >> 4;   // 16x16 compute grid, 8x8 frags
    int fr = tid >> 1;                  // A fill row 0..127
    int fq = tid & 1;                   // A fill k-half (16 floats)
    int br = tid >> 3;                  // B fill k-row 0..31
    int bo = (tid & 7) * 16;            // B fill float offset (64B)
    float local_loss = 0.0f;

    for (;;) {
        if (tid == 0) s_work = atomicAdd(&g_ticket, 1);
        __syncthreads();
        int w = s_work;
        if (w >= g_nwork) break;
        int wk   = g_work[w];
        int type = wk >> 8;
        int row0 = (wk & 255) * 128;
        int cnt  = g_count[type];
        int rows = min(128, cnt - row0);

        if (tid < 128) {
            int r = (tid < rows) ? tid : (rows - 1);
            toks[tid]  = g_order[g_offset[type] + row0 + r];
            snorm[tid] = 0.0f;
            sen2[tid]  = g_en2[type * PER + tid];
        }
        __syncthreads();

        const float* xrow   = x + (size_t)toks[fr] * DIM + fq * 16;
        const float* bTbase = g_ebT + (size_t)type * DIM * PER;

        float acc[8][8];
        #pragma unroll
        for (int i = 0; i < 8; i++)
            #pragma unroll
            for (int j = 0; j < 8; j++) acc[i][j] = 0.0f;

        float4 xa[4];
        // ---- prologue: chunk 0 ----
        #pragma unroll
        for (int u = 0; u < 4; u++) xa[u] = *(const float4*)(xrow + 4 * u);
        {
            const float* bsrc = bTbase + (size_t)br * PER + bo;
            uint32_t bdst = smem_u32(&dynsm[8192 + br * 128 + bo]);
            #pragma unroll
            for (int q = 0; q < 4; q++) CP_ASYNC16(bdst + 16*q, bsrc + 4*q);
            CP_COMMIT();
        }
        {
            float ps = 0.0f;
            #pragma unroll
            for (int u = 0; u < 4; u++) {
                float4 v = xa[u];
                ps += v.x*v.x + v.y*v.y + v.z*v.z + v.w*v.w;
                int kb = fq * 16 + 4 * u;
                dynsm[(kb+0)*128 + fr] = v.x; dynsm[(kb+1)*128 + fr] = v.y;
                dynsm[(kb+2)*128 + fr] = v.z; dynsm[(kb+3)*128 + fr] = v.w;
            }
            atomicAdd(&snorm[fr], ps);
        }
        CP_WAIT0();
        __syncthreads();

        int p = 0;
        for (int ch = 0; ch < NCHUNK; ch++) {
            float* As  = dynsm + (p ? 4096 : 0);
            float* Bs  = dynsm + 8192 + (p ? 4096 : 0);
            float* Asn = dynsm + (p ? 0 : 4096);
            float* Bsn = dynsm + 8192 + (p ? 0 : 4096);
            bool more = (ch + 1 < NCHUNK);
            if (more) {
                int k0n = (ch + 1) * KC;
                const float* bsrc = bTbase + (size_t)(k0n + br) * PER + bo;
                uint32_t bdst = smem_u32(&Bsn[br * 128 + bo]);
                #pragma unroll
                for (int q = 0; q < 4; q++) CP_ASYNC16(bdst + 16*q, bsrc + 4*q);
                CP_COMMIT();
                #pragma unroll
                for (int u = 0; u < 4; u++)
                    xa[u] = *(const float4*)(xrow + k0n + 4 * u);
            }

            // --- scalar FFMA inner (R5, best measured FMA rate) ---
            #pragma unroll
            for (int kk = 0; kk < KC; kk++) {
                float4 a0 = *(const float4*)&As[kk*128 + ty*4];
                float4 a1 = *(const float4*)&As[kk*128 + 64 + ty*4];
                float4 b0 = *(const float4*)&Bs[kk*128 + tx*4];
                float4 b1 = *(const float4*)&Bs[kk*128 + 64 + tx*4];
                float a[8] = {a0.x,a0.y,a0.z,a0.w,a1.x,a1.y,a1.z,a1.w};
                float b[8] = {b0.x,b0.y,b0.z,b0.w,b1.x,b1.y,b1.z,b1.w};
                #pragma unroll
                for (int i = 0; i < 8; i++)
                    #pragma unroll
                    for (int j = 0; j < 8; j++)
                        acc[i][j] = fmaf(a[i], b[j], acc[i][j]);
            }

            if (more) {
                float ps = 0.0f;
                #pragma unroll
                for (int u = 0; u < 4; u++) {
                    float4 v = xa[u];
                    ps += v.x*v.x + v.y*v.y + v.z*v.z + v.w*v.w;
                    int kb = fq * 16 + 4 * u;
                    Asn[(kb+0)*128 + fr] = v.x; Asn[(kb+1)*128 + fr] = v.y;
                    Asn[(kb+2)*128 + fr] = v.z; Asn[(kb+3)*128 + fr] = v.w;
                }
                atomicAdd(&snorm[fr], ps);
            }
            CP_WAIT0();
            __syncthreads();
            p ^= 1;
        }

        // --- epilogue: argmin + loss + idx tail (R5-validated) ---
        #pragma unroll
        for (int i = 0; i < 8; i++) {
            int m = (i < 4) ? (ty*4 + i) : (64 + ty*4 + (i - 4));
            float invn = 1.0f / fmaxf(sqrtf(snorm[m]), 1e-12f);
            float best = FLT_MAX; int bc = 1 << 30;
            #pragma unroll
            for (int j = 0; j < 8; j++) {
                int c = (j < 4) ? (tx*4 + j) : (64 + tx*4 + (j - 4));
                float s = sen2[c] - 2.0f * invn * acc[i][j];
                if (s < best || (s == best && c < bc)) { best = s; bc = c; }
            }
            #pragma unroll
            for (int o = 8; o; o >>= 1) {
                float s2 = __shfl_xor_sync(0xffffffffu, best, o);
                int   c2 = __shfl_xor_sync(0xffffffffu, bc,   o);
                if (s2 < best || (s2 == best && c2 < bc)) { best = s2; bc = c2; }
            }
            if (tx == 0 && m < rows) {
                int tok  = toks[m];
                int code = type * PER + bc;
                scodes[m] = code;
                out[ND + 2 + tok] = (float)code;
                float e2 = sen2[bc];
                local_loss += 2.0f - (e2 - best) / sqrtf(e2);
            }
        }
        __syncthreads();

        // --- fused finalize: out row = g_ne[code] ---
        if (fr < rows) {
            const float4* src = (const float4*)(g_ne + (size_t)scodes[fr] * DIM) + fq * 64;
            float4*       dst = (float4*)(out + (size_t)toks[fr] * DIM) + fq * 64;
            #pragma unroll 8
            for (int q = 0; q < 64; q++) dst[q] = src[q];
        }
        // loop-top __syncthreads orders copy before smem/toks reuse
    }

    // --- commit local commit-loss ---
    red[tid] = local_loss;
    __syncthreads();
    for (int s = 128; s; s >>= 1) {
        if (tid < s) red[tid] += red[tid + s];
        __syncthreads();
    }
    if (tid == 0 && red[0] != 0.0f) atomicAdd(&g_diff_acc, (double)red[0]);
    __syncthreads();

    // --- tail: uloss rows via second ticket (slowest-CTA shadow) ---
    float* si = dynsm;
    int wwarp = tid >> 5, lane = tid & 31;
    for (;;) {
        if (tid == 0) s_work = atomicAdd(&g_uticket, 1);
        __syncthreads();
        int i = s_work;
        if (i >= SAMP) break;
        int si_idx = samp[i];
        if (tid < 128)
            ((float4*)si)[tid] = ((const float4*)(g_ne + (size_t)si_idx * DIM))[tid];
        __syncthreads();
        int lab_i = si_idx / PER;
        float sum = 0.0f, pos = 0.0f;
        for (int j = wwarp; j < SAMP; j += 8) {
            int sj = samp[j];
            const float* vj = g_ne + (size_t)sj * DIM;
            float p = 0.0f;
            #pragma unroll 4
            for (int d = lane; d < DIM; d += 32) p = fmaf(si[d], vj[d], p);
            #pragma unroll
            for (int o = 16; o; o >>= 1) p += __shfl_xor_sync(0xffffffffu, p, o);
            if (lane == 0 && j != i) {
                float e = expf(p / TEMP);
                sum += e;
                if (sj / PER == lab_i) pos += e;
            }
        }
        if (lane == 0) { wsum[wwarp] = sum; wpos[wwarp] = pos; }
        __syncthreads();
        if (tid == 0) {
            float S = 0.0f, P = 0.0f;
            #pragma unroll
            for (int k = 0; k < 8; k++) { S += wsum[k]; P += wpos[k]; }
            atomicAdd(&g_uloss_acc, (double)(-logf(P / S)));
        }
        __syncthreads();
    }

    // --- last CTA writes scalars ---
    if (tid == 0) {
        __threadfence();
        int d = atomicAdd(&g_ctadone, 1);
        if (d == (int)gridDim.x - 1) {
            double diff = atomicAdd(&g_diff_acc, 0.0);
            double u    = atomicAdd(&g_uloss_acc, 0.0);
            out[ND]     = (float)((1.0 + (double)COMMIT) * diff / (double)ND);
            out[ND + 1] = (float)(u / (double)SAMP);
        }
    }
}

// -------- launch --------
extern "C" void kernel_launch(void* const* d_in, const int* in_sizes, int n_in,
                              void* d_out, int out_size) {
    const float* x    = (const float*)d_in[0];
    const float* emb  = (const float*)d_in[1];
    const int*   Q    = (const int*)d_in[2];
    const int*   samp = (const int*)d_in[3];
    float* out = (float*)d_out;

    cudaFuncSetAttribute(k_argmin, cudaFuncAttributeMaxDynamicSharedMemorySize, 65536);

    k_init<<<1, 32>>>();
    k_norm_emb<<<NCODE, 128>>>(emb);
    k_histscat<<<64, 256>>>(Q);
    k_argmin<<<296, 256, 65536>>>(x, samp, out);
}

// round 16
// speedup vs baseline: 1.0948x; 1.0948x over previous
#include <cuda_runtime.h>
#include <float.h>
#include <math.h>
#include <stdint.h>

// Problem constants
#define N_TOK   32768
#define DIM     512
#define NTYPE   26
#define PER     128
#define NCODE   (NTYPE*PER)     // 3328
#define SAMP    312
#define ND      (N_TOK*DIM)     // 16777216
#define TEMP    0.07f
#define COMMIT  0.25f
#define KC      32
#define NCTA    296             // 148 SMs x 2 resident CTAs

// -------- scratch (device globals; no allocation allowed) --------
__device__ float  g_ne[NCODE*DIM];     // normalized embeddings
__device__ float  g_en2[NCODE];        // ||emb_j||^2
__device__ int    g_count[NTYPE];
__device__ int    g_offset[NTYPE];
__device__ int    g_cursor[NTYPE];
__device__ int    g_order[N_TOK];
__device__ int    g_work[512];         // (type<<8)|tile worklist
__device__ int    g_nwork;
__device__ int    g_ticket;
__device__ int    g_uticket;
__device__ int    g_ctadone;
__device__ int    g_bar1;
__device__ int    g_bar2;
__device__ int    g_bar3;
__device__ double g_diff_acc;
__device__ double g_uloss_acc;

// -------- packed f32x2 helpers (validated R4/R10) --------
__device__ __forceinline__ void ffma2(unsigned long long &d,
                                      unsigned long long a,
                                      unsigned long long b) {
    asm("fma.rn.f32x2 %0, %1, %2, %0;" : "+l"(d) : "l"(a), "l"(b));
}
__device__ __forceinline__ unsigned long long packdup(float v) {
    unsigned long long r;
    asm("mov.b64 %0, {%1, %1};" : "=l"(r) : "f"(v));
    return r;
}
__device__ __forceinline__ float f2lo(unsigned long long v) {
    return __uint_as_float((unsigned)(v & 0xffffffffull));
}
__device__ __forceinline__ float f2hi(unsigned long long v) {
    return __uint_as_float((unsigned)(v >> 32));
}

// grid-wide spin barrier (all CTAs resident by construction)
__device__ __forceinline__ void gbar(int* ctr, int tid) {
    __syncthreads();
    if (tid == 0) {
        __threadfence();
        atomicAdd(ctr, 1);
        while (atomicAdd(ctr, 0) < NCTA) {}
    }
    __syncthreads();
}

// -------- kernels --------
__global__ void k_init() {
    int t = threadIdx.x;
    if (t < NTYPE) g_count[t] = 0;
    if (t == 0) {
        g_diff_acc = 0.0; g_uloss_acc = 0.0;
        g_ticket = 0; g_uticket = 0; g_ctadone = 0;
        g_bar1 = 0; g_bar2 = 0; g_bar3 = 0;
    }
}

// ONE persistent kernel: norm+hist -> scan -> scatter -> GEMM+argmin -> uloss.
__global__ __launch_bounds__(256, 2) void k_mega(const float* __restrict__ x,
                                                 const float* __restrict__ emb,
                                                 const int* __restrict__ Q,
                                                 const int* __restrict__ samp,
                                                 float* __restrict__ out) {
    __shared__ __align__(16) float As[KC][128];   // [k][token]
    __shared__ __align__(16) float Bs[KC][128];   // [k][code]
    __shared__ int   toks[128];
    __shared__ float snorm[128];
    __shared__ float sen2[128];
    __shared__ int   scodes[128];
    __shared__ int   s_work;
    __shared__ float red[256];
    __shared__ float nws[2][4];
    __shared__ int   h[NTYPE], hbase[NTYPE];
    __shared__ float wsum[8], wpos[8];

    int tid = threadIdx.x;

    // ===== phase 0a: histogram over this CTA's token range =====
    if (tid < NTYPE) h[tid] = 0;
    __syncthreads();
    int per = (N_TOK + NCTA - 1) / NCTA;   // 111
    int ts = blockIdx.x * per;
    int te = min(ts + per, N_TOK);
    for (int i = ts + tid; i < te; i += 256)
        atomicAdd(&h[Q[i]], 1);
    __syncthreads();
    if (tid < NTYPE && h[tid]) atomicAdd(&g_count[tid], h[tid]);

    // ===== phase 0b: emb norm (2 rows per iteration, 128 thr each) =====
    {
        int half = tid >> 7, ht = tid & 127, hw = ht >> 5, hl = ht & 31;
        for (int row = blockIdx.x * 2 + half; row < NCODE; row += NCTA * 2) {
            float4 a = ((const float4*)(emb + (size_t)row * DIM))[ht];
            float s = a.x*a.x + a.y*a.y + a.z*a.z + a.w*a.w;
            #pragma unroll
            for (int o = 16; o; o >>= 1) s += __shfl_xor_sync(0xffffffffu, s, o);
            if (hl == 0) nws[half][hw] = s;
            __syncthreads();
            float tot = nws[half][0] + nws[half][1] + nws[half][2] + nws[half][3];
            if (ht == 0) g_en2[row] = tot;
            float inv = 1.0f / fmaxf(sqrtf(tot), 1e-12f);
            ((float4*)(g_ne + (size_t)row * DIM))[ht] =
                make_float4(a.x*inv, a.y*inv, a.z*inv, a.w*inv);
            __syncthreads();
        }
    }

    gbar(&g_bar1, tid);

    // ===== phase 1: CTA0 scan + worklist =====
    if (blockIdx.x == 0 && tid < 32) {
        int lane = tid;
        int c = (lane < NTYPE) ? g_count[lane] : 0;
        int tiles = (c + 127) / 128;
        int sc = c, st = tiles;
        #pragma unroll
        for (int o = 1; o < 32; o <<= 1) {
            int v = __shfl_up_sync(0xffffffffu, sc, o);
            int w = __shfl_up_sync(0xffffffffu, st, o);
            if (lane >= o) { sc += v; st += w; }
        }
        int off = sc - c, toff = st - tiles;
        if (lane < NTYPE) {
            g_offset[lane] = off;
            g_cursor[lane] = off;
            for (int t2 = 0; t2 < tiles; t2++) g_work[toff + t2] = (lane << 8) | t2;
        }
        int tot = __shfl_sync(0xffffffffu, st, NTYPE - 1);
        if (lane == 0) g_nwork = tot;
    }

    gbar(&g_bar2, tid);

    // ===== phase 2: block-aggregated scatter (reuses h from phase 0a) =====
    if (tid < NTYPE) {
        hbase[tid] = (h[tid] > 0) ? atomicAdd(&g_cursor[tid], h[tid]) : 0;
        h[tid] = 0;
    }
    __syncthreads();
    for (int i = ts + tid; i < te; i += 256) {
        int t = Q[i];
        g_order[hbase[t] + atomicAdd(&h[t], 1)] = i;
    }

    gbar(&g_bar3, tid);

    // ===== phase 3: R10 GEMM + argmin + loss + idx + copy (verbatim) =====
    int tx = tid & 15, ty = tid >> 4;
    int fr = tid >> 1;
    int fq = tid & 1;
    float local_loss = 0.0f;

    for (;;) {
        if (tid == 0) s_work = atomicAdd(&g_ticket, 1);
        __syncthreads();
        int w = s_work;
        if (w >= g_nwork) break;
        int wk   = g_work[w];
        int type = wk >> 8;
        int row0 = (wk & 255) * 128;
        int cnt  = g_count[type];
        int rows = min(128, cnt - row0);

        if (tid < 128) {
            int r = (tid < rows) ? tid : (rows - 1);
            toks[tid]  = g_order[g_offset[type] + row0 + r];
            snorm[tid] = 0.0f;
            sen2[tid]  = g_en2[type * PER + tid];
        }
        __syncthreads();

        const float* xrow = x   + (size_t)toks[fr] * DIM + fq * 16;
        const float* brow = emb + (size_t)(type * PER + fr) * DIM + fq * 16;

        unsigned long long acc[8][4];
        #pragma unroll
        for (int i = 0; i < 8; i++)
            #pragma unroll
            for (int s = 0; s < 4; s++) acc[i][s] = 0ull;

        for (int k0 = 0; k0 < DIM; k0 += KC) {
            float ps = 0.0f;
            #pragma unroll
            for (int u = 0; u < 4; u++) {
                float4 v = *(const float4*)(xrow + k0 + 4 * u);
                ps += v.x*v.x + v.y*v.y + v.z*v.z + v.w*v.w;
                int kb = fq * 16 + 4 * u;
                As[kb+0][fr] = v.x; As[kb+1][fr] = v.y;
                As[kb+2][fr] = v.z; As[kb+3][fr] = v.w;
            }
            atomicAdd(&snorm[fr], ps);
            #pragma unroll
            for (int u = 0; u < 4; u++) {
                float4 v = *(const float4*)(brow + k0 + 4 * u);
                int kb = fq * 16 + 4 * u;
                Bs[kb+0][fr] = v.x; Bs[kb+1][fr] = v.y;
                Bs[kb+2][fr] = v.z; Bs[kb+3][fr] = v.w;
            }
            __syncthreads();

            #pragma unroll
            for (int kk = 0; kk < KC; kk++) {
                float4 a0 = *(const float4*)&As[kk][ty*4];
                float4 a1 = *(const float4*)&As[kk][64 + ty*4];
                unsigned long long av[8];
                av[0] = packdup(a0.x); av[1] = packdup(a0.y);
                av[2] = packdup(a0.z); av[3] = packdup(a0.w);
                av[4] = packdup(a1.x); av[5] = packdup(a1.y);
                av[6] = packdup(a1.z); av[7] = packdup(a1.w);
                const unsigned long long* Br =
                    (const unsigned long long*)&Bs[kk][0];
                unsigned long long bv[4];
                #pragma unroll
                for (int s = 0; s < 4; s++) bv[s] = Br[tx + 16*s];
                #pragma unroll
                for (int i = 0; i < 8; i++)
                    #pragma unroll
                    for (int s = 0; s < 4; s++)
                        ffma2(acc[i][s], av[i], bv[s]);
            }
            __syncthreads();
        }

        #pragma unroll
        for (int i = 0; i < 8; i++) {
            int m = (i < 4) ? (ty*4 + i) : (64 + ty*4 + (i - 4));
            float invn = 1.0f / fmaxf(sqrtf(snorm[m]), 1e-12f);
            float best = FLT_MAX; int bc = 1 << 30;
            #pragma unroll
            for (int s = 0; s < 4; s++) {
                int j0 = 2*tx + 32*s;
                float sc0 = sen2[j0]   - 2.0f * invn * f2lo(acc[i][s]);
                float sc1 = sen2[j0+1] - 2.0f * invn * f2hi(acc[i][s]);
                if (sc0 < best || (sc0 == best && j0 < bc))   { best = sc0; bc = j0; }
                if (sc1 < best || (sc1 == best && j0+1 < bc)) { best = sc1; bc = j0+1; }
            }
            #pragma unroll
            for (int o = 8; o; o >>= 1) {
                float s2 = __shfl_xor_sync(0xffffffffu, best, o);
                int   c2 = __shfl_xor_sync(0xffffffffu, bc,   o);
                if (s2 < best || (s2 == best && c2 < bc)) { best = s2; bc = c2; }
            }
            if (tx == 0 && m < rows) {
                int tok  = toks[m];
                int code = type * PER + bc;
                scodes[m] = code;
                out[ND + 2 + tok] = (float)code;
                float e2 = sen2[bc];
                local_loss += 2.0f - (e2 - best) / sqrtf(e2);
            }
        }
        __syncthreads();

        if (fr < rows) {
            const float4* src = (const float4*)(g_ne + (size_t)scodes[fr] * DIM) + fq * 64;
            float4*       dst = (float4*)(out + (size_t)toks[fr] * DIM) + fq * 64;
            #pragma unroll 8
            for (int q = 0; q < 64; q++) dst[q] = src[q];
        }
    }

    // ===== commit commit-loss =====
    red[tid] = local_loss;
    __syncthreads();
    for (int s = 128; s; s >>= 1) {
        if (tid < s) red[tid] += red[tid + s];
        __syncthreads();
    }
    if (tid == 0 && red[0] != 0.0f) atomicAdd(&g_diff_acc, (double)red[0]);
    __syncthreads();

    // ===== phase 4: uloss tail (second ticket, slowest-CTA shadow) =====
    float* si = &As[0][0];
    int wwarp = tid >> 5, lane = tid & 31;
    for (;;) {
        if (tid == 0) s_work = atomicAdd(&g_uticket, 1);
        __syncthreads();
        int i = s_work;
        if (i >= SAMP) break;
        int si_idx = samp[i];
        if (tid < 128)
            ((float4*)si)[tid] = ((const float4*)(g_ne + (size_t)si_idx * DIM))[tid];
        __syncthreads();
        int lab_i = si_idx / PER;
        float sum = 0.0f, pos = 0.0f;
        for (int j = wwarp; j < SAMP; j += 8) {
            int sj = samp[j];
            const float* vj = g_ne + (size_t)sj * DIM;
            float p = 0.0f;
            #pragma unroll 4
            for (int d = lane; d < DIM; d += 32) p = fmaf(si[d], vj[d], p);
            #pragma unroll
            for (int o = 16; o; o >>= 1) p += __shfl_xor_sync(0xffffffffu, p, o);
            if (lane == 0 && j != i) {
                float e = expf(p / TEMP);
                sum += e;
                if (sj / PER == lab_i) pos += e;
            }
        }
        if (lane == 0) { wsum[wwarp] = sum; wpos[wwarp] = pos; }
        __syncthreads();
        if (tid == 0) {
            float S = 0.0f, P = 0.0f;
            #pragma unroll
            for (int k = 0; k < 8; k++) { S += wsum[k]; P += wpos[k]; }
            atomicAdd(&g_uloss_acc, (double)(-logf(P / S)));
        }
        __syncthreads();
    }

    // ===== last CTA writes scalars =====
    if (tid == 0) {
        __threadfence();
        int d = atomicAdd(&g_ctadone, 1);
        if (d == NCTA - 1) {
            double diff = atomicAdd(&g_diff_acc, 0.0);
            double u    = atomicAdd(&g_uloss_acc, 0.0);
            out[ND]     = (float)((1.0 + (double)COMMIT) * diff / (double)ND);
            out[ND + 1] = (float)(u / (double)SAMP);
        }
    }
}

// -------- launch --------
extern "C" void kernel_launch(void* const* d_in, const int* in_sizes, int n_in,
                              void* d_out, int out_size) {
    const float* x    = (const float*)d_in[0];
    const float* emb  = (const float*)d_in[1];
    const int*   Q    = (const int*)d_in[2];
    const int*   samp = (const int*)d_in[3];
    float* out = (float*)d_out;

    k_init<<<1, 32>>>();
    k_mega<<<NCTA, 256>>>(x, emb, Q, samp, out);
}